// round 16
// baseline (speedup 1.0000x reference)
#include <cuda_runtime.h>
#include <cuda_bf16.h>
#include <cstdint>

#define NN 50000
#define D 128
#define NK 4
#define NT 2
#define NE 100000
#define NOHL 3
#define KD1 131
#define TR 128
#define MTHR 512
typedef unsigned long long ull;

// ---------------- helpers ----------------
static __device__ __forceinline__ uint32_t stou(const void* p){
    uint32_t a; asm("{ .reg .u64 t; cvta.to.shared.u64 t, %1; cvt.u32.u64 %0, t; }"
                    : "=r"(a) : "l"(p)); return a;
}
static __device__ __forceinline__ float sigf(float x){
    float t; asm("tanh.approx.f32 %0, %1;" : "=f"(t) : "f"(x * 0.5f));
    return 0.5f * t + 0.5f;
}
static __device__ __forceinline__ uint32_t pkbf(float lo, float hi){
    uint32_t r; asm("cvt.rn.bf16x2.f32 %0, %1, %2;" : "=r"(r) : "f"(hi), "f"(lo)); return r;
}
static __device__ __forceinline__ void bfsplit(float x, float y, uint32_t& hi, uint32_t& lo){
    hi = pkbf(x, y);
    float xh = __uint_as_float(hi << 16);
    float yh = __uint_as_float(hi & 0xFFFF0000u);
    lo = pkbf(x - xh, y - yh);
}
static __device__ __forceinline__ uint32_t sw128(uint32_t o){ return o ^ ((o >> 3) & 0x70); }
static __device__ __forceinline__ void cp16(unsigned s, const void* g){
    asm volatile("cp.async.cg.shared.global [%0], [%1], 16;" :: "r"(s), "l"(g));
}
static __device__ __forceinline__ void cp_commit(){ asm volatile("cp.async.commit_group;" ::: "memory"); }
static __device__ __forceinline__ void cp_wait0(){ asm volatile("cp.async.wait_group 0;" ::: "memory"); }

#define MMA(d, a, b) asm volatile( \
    "mma.sync.aligned.m16n8k16.row.col.f32.bf16.bf16.f32 " \
    "{%0,%1,%2,%3}, {%4,%5,%6,%7}, {%8,%9}, {%0,%1,%2,%3};" \
    : "+f"((d)[0]), "+f"((d)[1]), "+f"((d)[2]), "+f"((d)[3]) \
    : "r"((a)[0]), "r"((a)[1]), "r"((a)[2]), "r"((a)[3]), "r"((b).x), "r"((b).y))
#define LDSM4(r, a) asm volatile( \
    "ldmatrix.sync.aligned.m8n8.x4.shared.b16 {%0,%1,%2,%3}, [%4];" \
    : "=r"((r)[0]), "=r"((r)[1]), "=r"((r)[2]), "=r"((r)[3]) : "r"(a))

// ---------------- prepped B fragments ----------------
// [mat(12)][term(2)][kt(8)*16+nt(16)][lane(32)] of uint2 (b0,b1); hi+lo contiguous per mat
__device__ uint2 g_Bf[12 * 2 * 4096];

__global__ void prep_kernel(const float* __restrict__ Wtr, const float* __restrict__ Wg1,
                            const float* __restrict__ Wg2){
    int id = blockIdx.x * 256 + threadIdx.x;
    if (id >= 12 * 8 * 16 * 32) return;
    int lane = id & 31, nt = (id >> 5) & 15, kt = (id >> 9) & 7, mat = id >> 12;
    int kk = mat / 3, m = mat % 3;
    const float* W = (m == 0) ? Wtr + (size_t)kk * KD1 * D
                   : (m == 1) ? Wg1 + (size_t)kk * KD1 * D
                              : Wg2 + (size_t)kk * D * D;
    int k0 = kt * 16 + (lane & 3) * 2;
    int n  = nt * 8 + (lane >> 2);
    uint32_t h0, l0, h1, l1;
    bfsplit(W[(size_t)k0 * D + n], W[(size_t)(k0 + 1) * D + n], h0, l0);
    bfsplit(W[(size_t)(k0 + 8) * D + n], W[(size_t)(k0 + 9) * D + n], h1, l1);
    int fo = (kt * 16 + nt) * 32 + lane;
    g_Bf[(mat * 2 + 0) * 4096 + fo] = make_uint2(h0, h1);
    g_Bf[(mat * 2 + 1) * 4096 + fo] = make_uint2(l0, l1);
}

// ---------------- smem map ----------------
#define O_AH   0
#define O_AL   32768
#define O_ST0  65536          // stage 0: [hi 32KB][lo 32KB]
#define O_ST1  131072         // stage 1
#define O_DEG  196608         // float4[128]
#define O_DEGW 198656         // float[2][3][128]
#define O_BIAS 201728         // float[3][128]
#define SM_MMA 203264

// fill one 64KB stage (hi+lo fragments of one matrix) via cp.async
static __device__ __forceinline__ void fill_stage(char* dst, int mat, int tid){
    unsigned d0 = stou(dst);
    const char* src = (const char*)(g_Bf + (size_t)mat * 8192);
    #pragma unroll 4
    for (int i = tid; i < 4096; i += MTHR)
        cp16(d0 + (unsigned)i * 16u, src + (size_t)i * 16);
    cp_commit();
}

// 3-term split-bf16 GEMM: 128x128x128; warp tile 32x32 (wr 0..3, wc 0..3); B from smem
static __device__ __forceinline__ void do_gemm(float (*acc)[4], uint32_t aH, uint32_t aL,
                                               const char* stage, int wr, int wc, int lane)
{
    const uint2* BfH = (const uint2*)stage;
    const uint2* BfL = BfH + 4096;
    #pragma unroll
    for (int i = 0; i < 8; ++i)
        #pragma unroll
        for (int j = 0; j < 4; ++j) acc[i][j] = 0.f;

    #pragma unroll 1
    for (int kt = 0; kt < 8; ++kt) {
        uint32_t ah[2][4], al[2][4];
        const int row = wr * 32 + (lane & 15);
        const int kk  = kt * 16 + (lane >> 4) * 8;
        const uint32_t soff = (uint32_t)(kk >> 6) * 16384u;
        #pragma unroll
        for (int mt = 0; mt < 2; ++mt) {
            uint32_t a = soff + sw128((uint32_t)((row + mt * 16) * 128 + (kk & 63) * 2));
            LDSM4(ah[mt], aH + a);
            LDSM4(al[mt], aL + a);
        }
        uint2 bh[4], bl[4];
        #pragma unroll
        for (int nt = 0; nt < 4; ++nt) {
            int fo = (kt * 16 + wc * 4 + nt) * 32 + lane;
            bh[nt] = BfH[fo];
            bl[nt] = BfL[fo];
        }
        #pragma unroll
        for (int mt = 0; mt < 2; ++mt)
            #pragma unroll
            for (int nt = 0; nt < 4; ++nt) {
                float* d = acc[mt * 4 + nt];
                MMA(d, ah[mt], bh[nt]);
                MMA(d, ah[mt], bl[nt]);
                MMA(d, al[mt], bh[nt]);
            }
    }
}

// epilogue: MODE 0 = sigmoid*prod (tr,deg), 1 = relu->A bf16 (g1,deg), 2 = sigmoid*prod (g2)
template<int MODE>
static __device__ __forceinline__ void epi(float (*acc)[4], float* prod,
                                           const float4* DEG, const float* DEGW,
                                           const float* BIAS,
                                           int wr, int wc, int lane, char* AH, char* AL)
{
    const float* BW = DEGW + (MODE == 1 ? 384 : 0);
    #pragma unroll
    for (int mt = 0; mt < 2; ++mt) {
        const int r0 = wr * 32 + mt * 16 + (lane >> 2);
        float4 dva, dvb;
        if (MODE != 2) { dva = DEG[r0]; dvb = DEG[r0 + 8]; }
        #pragma unroll
        for (int nt = 0; nt < 4; ++nt) {
            const int c0 = wc * 32 + nt * 8 + 2 * (lane & 3);
            const float b0 = BIAS[MODE * 128 + c0], b1 = BIAS[MODE * 128 + c0 + 1];
            float* a = acc[mt * 4 + nt];
            float x0 = a[0] + b0, x1 = a[1] + b1, x2 = a[2] + b0, x3 = a[3] + b1;
            if (MODE != 2) {
                float w00 = BW[c0], w01 = BW[c0 + 1];
                float w10 = BW[128 + c0], w11 = BW[128 + c0 + 1];
                float w20 = BW[256 + c0], w21 = BW[256 + c0 + 1];
                x0 += dva.x * w00 + dva.y * w10 + dva.z * w20;
                x1 += dva.x * w01 + dva.y * w11 + dva.z * w21;
                x2 += dvb.x * w00 + dvb.y * w10 + dvb.z * w20;
                x3 += dvb.x * w01 + dvb.y * w11 + dvb.z * w21;
            }
            if (MODE == 1) {
                uint32_t hi, lo;
                uint32_t oa = (uint32_t)(c0 >> 6) * 16384u + sw128((uint32_t)(r0 * 128 + (c0 & 63) * 2));
                bfsplit(fmaxf(x0, 0.f), fmaxf(x1, 0.f), hi, lo);
                *(uint32_t*)(AH + oa) = hi; *(uint32_t*)(AL + oa) = lo;
                uint32_t ob = (uint32_t)(c0 >> 6) * 16384u + sw128((uint32_t)((r0 + 8) * 128 + (c0 & 63) * 2));
                bfsplit(fmaxf(x2, 0.f), fmaxf(x3, 0.f), hi, lo);
                *(uint32_t*)(AH + ob) = hi; *(uint32_t*)(AL + ob) = lo;
            } else {
                float* p = prod + (mt * 4 + nt) * 4;
                p[0] *= sigf(x0); p[1] *= sigf(x1); p[2] *= sigf(x2); p[3] *= sigf(x3);
            }
        }
    }
}

// ---------------------------------------------------------------------------
// Fused warp-MMA kernel, 512 threads (16 warps, 4/SMSP). grid = (ceil(E/128), K).
// ---------------------------------------------------------------------------
__global__ void __launch_bounds__(MTHR)
gnn_mma_kernel(const float* __restrict__ h, const int* __restrict__ pairs,
               const float* __restrict__ degrees, const int* __restrict__ scat,
               const float* __restrict__ W_tr, const float* __restrict__ b_tr,
               const float* __restrict__ W_g1, const float* __restrict__ b_g1,
               const float* __restrict__ W_g2, const float* __restrict__ b_g2,
               const float* __restrict__ eps, float* __restrict__ out)
{
    extern __shared__ char smc[];
    char* AH = smc + O_AH;  char* AL = smc + O_AL;
    float4* DEG = (float4*)(smc + O_DEG);
    float* DEGW = (float*)(smc + O_DEGW);
    float* BIAS = (float*)(smc + O_BIAS);

    const int tid = threadIdx.x, lane = tid & 31, warp = tid >> 5;
    const int wr = warp >> 2, wc = warp & 3;
    const int e0 = blockIdx.x * TR, k = blockIdx.y;
    const uint32_t aHs = stou(AH), aLs = stou(AL);

    for (int i = tid; i < 384; i += MTHR) {
        DEGW[i]       = W_tr[(size_t)k * KD1 * D + 128 * D + i];
        DEGW[384 + i] = W_g1[(size_t)k * KD1 * D + 128 * D + i];
    }
    if (tid < 128) {
        BIAS[tid]       = b_tr[k * D + tid];
        BIAS[128 + tid] = b_g1[k * D + tid];
        BIAS[256 + tid] = b_g2[k * D + tid];
    }
    fill_stage(smc + O_ST0, k * 3 + 0, tid);   // tr -> st0

    float prod[32];
    #pragma unroll
    for (int i = 0; i < 32; ++i) prod[i] = 1.0f;
    float acc[8][4];

    for (int it = 0; it < NT; ++it) {
        char* stA = smc + ((it & 1) ? O_ST1 : O_ST0);   // tr (then g2)
        char* stB = smc + ((it & 1) ? O_ST0 : O_ST1);   // g1
        __syncthreads();                        // prev-iter A/stage reads done
        // ---- gather ht -> AH/AL (bf16 split), deg -> DEG. 4 threads/row ----
        {
            int r = tid >> 2, sub = tid & 3;
            int e = e0 + r;
            int row = (e < NE) ? pairs[(k * NT + it) * NE + e] : -1;
            const float4* src = (const float4*)(h + (size_t)(row < 0 ? 0 : row) * D) + 8 * sub;
            #pragma unroll
            for (int q = 0; q < 8; ++q) {
                float4 v = (row >= 0) ? src[q] : make_float4(0.f, 0.f, 0.f, 0.f);
                int kd = sub * 32 + 4 * q;
                uint32_t h0, l0, h1, l1;
                bfsplit(v.x, v.y, h0, l0);
                bfsplit(v.z, v.w, h1, l1);
                uint32_t off = (uint32_t)(kd >> 6) * 16384u + sw128((uint32_t)(r * 128 + (kd & 63) * 2));
                *(uint2*)(AH + off) = make_uint2(h0, h1);
                *(uint2*)(AL + off) = make_uint2(l0, l1);
            }
            if (sub == 0) {
                float4 dv = make_float4(0.f, 0.f, 0.f, 0.f);
                if (e < NE) {
                    const float* dp = degrees + ((size_t)(k * NT + it) * NE + e) * NOHL;
                    dv.x = dp[0]; dv.y = dp[1]; dv.z = dp[2];
                }
                DEG[r] = dv;
            }
        }
        cp_wait0();          // stage A (tr) resident
        __syncthreads();     // + gathered A visible

        fill_stage(stB, k * 3 + 1, tid);        // g1 -> stB (overlaps GEMM1)
        do_gemm(acc, aHs, aLs, stA, wr, wc, lane);   // GEMM1: tr
        cp_wait0(); __syncthreads();            // stB ready; GEMM1 reads of stA done
        epi<0>(acc, prod, DEG, DEGW, BIAS, wr, wc, lane, AH, AL);

        fill_stage(stA, k * 3 + 2, tid);        // g2 -> stA (overlaps GEMM2)
        do_gemm(acc, aHs, aLs, stB, wr, wc, lane);   // GEMM2: g1
        cp_wait0();
        __syncthreads();                        // all A reads done + stA(g2) ready
        epi<1>(acc, prod, DEG, DEGW, BIAS, wr, wc, lane, AH, AL);   // g1 -> A
        __syncthreads();                        // A writes visible; GEMM2 stB reads done

        if (it + 1 < NT) fill_stage(stB, k * 3 + 0, tid);   // tr -> stB for next it
        do_gemm(acc, aHs, aLs, stA, wr, wc, lane);   // GEMM3: g2
        epi<2>(acc, prod, DEG, DEGW, BIAS, wr, wc, lane, AH, AL);
    }

    // ---- scatter-add ----
    const float sc = 1.0f + __ldg(eps + k);
    #pragma unroll
    for (int mt = 0; mt < 2; ++mt)
        #pragma unroll
        for (int hr = 0; hr < 2; ++hr) {
            int r = wr * 32 + mt * 16 + (lane >> 2) + hr * 8;
            int e = e0 + r;
            if (e < NE) {
                int idx = __ldg(scat + k * NE + e);
                float* base = out + (size_t)idx * D;
                #pragma unroll
                for (int nt = 0; nt < 4; ++nt) {
                    int c0 = wc * 32 + nt * 8 + 2 * (lane & 3);
                    float v0 = prod[(mt * 4 + nt) * 4 + hr * 2] * sc;
                    float v1 = prod[(mt * 4 + nt) * 4 + hr * 2 + 1] * sc;
                    asm volatile("red.global.add.v2.f32 [%0], {%1,%2};"
                                 :: "l"(base + c0), "f"(v0), "f"(v1) : "memory");
                }
            }
        }
}

// ======================= lin kernel (R6-proven) =======================
#define LTILE 128
#define LAST  132
#define LTHR  512
#define L_AS  (D * LAST)
#define L_BUF (D * 64)
#define SM_L  ((L_AS + 2 * L_BUF) * 4)

static __device__ __forceinline__ ull dup2(float v){
    ull r; asm("mov.b64 %0, {%1, %1};" : "=l"(r) : "f"(v)); return r;
}
static __device__ __forceinline__ void upk2(ull v, float &lo, float &hi){
    asm("mov.b64 {%0, %1}, %2;" : "=f"(lo), "=f"(hi) : "l"(v));
}
static __device__ __forceinline__ ull ffma2(ull a, ull b, ull c){
    ull d; asm("fma.rn.f32x2 %0, %1, %2, %3;" : "=l"(d) : "l"(a), "l"(b), "l"(c));
    return d;
}
__global__ void __launch_bounds__(LTHR, 1)
gnn_lin_kernel(const float* __restrict__ h, const float* __restrict__ W,
               const float* __restrict__ b, float* __restrict__ out)
{
    extern __shared__ float sm[];
    float* As = sm; float* buf0 = As + L_AS; float* buf1 = buf0 + L_BUF;
    const int tid = threadIdx.x, lane = tid & 31, rr = (tid >> 5) * 8;
    const int r0 = blockIdx.x * LTILE;
    {
        int r = tid >> 2, sub = tid & 3, row = r0 + r;
        #pragma unroll
        for (int q = 0; q < 8; ++q) {
            const int c = 32 * sub + 4 * q;
            const int pr = r ^ (((c >> 3) & 7) << 2);
            float* dst = As + c * LAST + pr;
            if (row < NN) {
                const float4 v = ((const float4*)(h + (size_t)row * D))[8 * sub + q];
                dst[0] = v.x; dst[LAST] = v.y; dst[2 * LAST] = v.z; dst[3 * LAST] = v.w;
            } else { dst[0] = 0.f; dst[LAST] = 0.f; dst[2 * LAST] = 0.f; dst[3 * LAST] = 0.f; }
        }
    }
    {
        const unsigned d0 = (unsigned)__cvta_generic_to_shared(buf0);
        for (int i = tid; i < D * 16; i += LTHR) {
            const int kk = i >> 4, c = i & 15;
            cp16(d0 + (unsigned)(kk * 64 + c * 4) * 4u, W + kk * D + c * 4);
        }
        cp_commit();
    }
    cp_wait0(); __syncthreads();
    ull acc[4][2];
    #pragma unroll
    for (int hh = 0; hh < 2; ++hh) {
        if (hh == 0) {
            const unsigned d1 = (unsigned)__cvta_generic_to_shared(buf1);
            for (int i = tid; i < D * 16; i += LTHR) {
                const int kk = i >> 4, c = i & 15;
                cp16(d1 + (unsigned)(kk * 64 + c * 4) * 4u, W + kk * D + 64 + c * 4);
            }
            cp_commit();
        }
        #pragma unroll
        for (int rp = 0; rp < 4; ++rp) { acc[rp][0] = 0ull; acc[rp][1] = 0ull; }
        const float* Wh = hh ? buf1 : buf0;
        #pragma unroll 4
        for (int kk = 0; kk < D; ++kk) {
            const int s4 = ((kk >> 3) & 7) << 2;
            const float* Ar = As + kk * LAST;
            const ulonglong2 alo = *(const ulonglong2*)(Ar + (rr ^ s4));
            const ulonglong2 ahi = *(const ulonglong2*)(Ar + ((rr + 4) ^ s4));
            const float2 bv = *(const float2*)(Wh + kk * 64 + 2 * lane);
            const ull b0 = dup2(bv.x), b1 = dup2(bv.y);
            const ull ap[4] = {alo.x, alo.y, ahi.x, ahi.y};
            #pragma unroll
            for (int rp = 0; rp < 4; ++rp) {
                acc[rp][0] = ffma2(ap[rp], b0, acc[rp][0]);
                acc[rp][1] = ffma2(ap[rp], b1, acc[rp][1]);
            }
        }
        const float2 bb = *(const float2*)(b + 64 * hh + 2 * lane);
        #pragma unroll
        for (int rp = 0; rp < 4; ++rp) {
            float l0, h0, l1, h1;
            upk2(acc[rp][0], l0, h0); upk2(acc[rp][1], l1, h1);
            const int row = r0 + rr + 2 * rp;
            if (row < NN)
                *(float2*)(out + (size_t)row * D + 64 * hh + 2 * lane) = make_float2(l0 + bb.x, l1 + bb.y);
            if (row + 1 < NN)
                *(float2*)(out + (size_t)(row + 1) * D + 64 * hh + 2 * lane) = make_float2(h0 + bb.x, h1 + bb.y);
        }
        if (hh == 0) { cp_wait0(); __syncthreads(); }
    }
}

// ---------------------------------------------------------------------------
extern "C" void kernel_launch(void* const* d_in, const int* in_sizes, int n_in,
                              void* d_out, int out_size)
{
    const float* h       = (const float*)d_in[0];
    const int*   pairs   = (const int*)  d_in[1];
    const float* degrees = (const float*)d_in[2];
    const int*   scat    = (const int*)  d_in[3];
    const float* W_lin   = (const float*)d_in[4];
    const float* b_lin   = (const float*)d_in[5];
    const float* W_tr    = (const float*)d_in[6];
    const float* b_tr    = (const float*)d_in[7];
    const float* W_g1    = (const float*)d_in[8];
    const float* b_g1    = (const float*)d_in[9];
    const float* W_g2    = (const float*)d_in[10];
    const float* b_g2    = (const float*)d_in[11];
    const float* eps     = (const float*)d_in[12];
    float* out = (float*)d_out;

    cudaFuncSetAttribute(gnn_lin_kernel, cudaFuncAttributeMaxDynamicSharedMemorySize, SM_L);
    cudaFuncSetAttribute(gnn_mma_kernel, cudaFuncAttributeMaxDynamicSharedMemorySize, SM_MMA);

    prep_kernel<<<192, 256>>>(W_tr, W_g1, W_g2);
    gnn_lin_kernel<<<(NN + LTILE - 1) / LTILE, LTHR, SM_L>>>(h, W_lin, b_lin, out);
    dim3 grid((NE + TR - 1) / TR, NK);
    gnn_mma_kernel<<<grid, MTHR, SM_MMA>>>(h, pairs, degrees, scat, W_tr, b_tr,
                                           W_g1, b_g1, W_g2, b_g2, eps, out);
}

// round 17
// speedup vs baseline: 1.8201x; 1.8201x over previous
#include <cuda_runtime.h>
#include <cuda_fp16.h>
#include <cstdint>

#define NN 50000
#define D 128
#define NK 4
#define NT 2
#define NE 100000
#define NOHL 3
#define KD1 131
#define TR 128
typedef unsigned long long ull;

// ---------------- helpers ----------------
static __device__ __forceinline__ uint32_t stou(const void* p){
    uint32_t a; asm("{ .reg .u64 t; cvta.to.shared.u64 t, %1; cvt.u32.u64 %0, t; }"
                    : "=r"(a) : "l"(p)); return a;
}
static __device__ __forceinline__ float sigf(float x){
    float t; asm("tanh.approx.f32 %0, %1;" : "=f"(t) : "f"(x * 0.5f));
    return 0.5f * t + 0.5f;
}
static __device__ __forceinline__ uint32_t pkhf(float lo, float hi){
    uint32_t r; asm("cvt.rn.f16x2.f32 %0, %1, %2;" : "=r"(r) : "f"(hi), "f"(lo)); return r;
}
static __device__ __forceinline__ uint32_t sw128(uint32_t o){ return o ^ ((o >> 3) & 0x70); }
static __device__ __forceinline__ void cp16(unsigned s, const void* g){
    asm volatile("cp.async.cg.shared.global [%0], [%1], 16;" :: "r"(s), "l"(g));
}
static __device__ __forceinline__ void cp_commit(){ asm volatile("cp.async.commit_group;" ::: "memory"); }
static __device__ __forceinline__ void cp_wait0(){ asm volatile("cp.async.wait_group 0;" ::: "memory"); }

#define MMA(d, a, b) asm volatile( \
    "mma.sync.aligned.m16n8k16.row.col.f32.f16.f16.f32 " \
    "{%0,%1,%2,%3}, {%4,%5,%6,%7}, {%8,%9}, {%0,%1,%2,%3};" \
    : "+f"((d)[0]), "+f"((d)[1]), "+f"((d)[2]), "+f"((d)[3]) \
    : "r"((a)[0]), "r"((a)[1]), "r"((a)[2]), "r"((a)[3]), "r"((b).x), "r"((b).y))
#define LDSM4(r, a) asm volatile( \
    "ldmatrix.sync.aligned.m8n8.x4.shared.b16 {%0,%1,%2,%3}, [%4];" \
    : "=r"((r)[0]), "=r"((r)[1]), "=r"((r)[2]), "=r"((r)[3]) : "r"(a))

// ---------------- prepped data ----------------
// B fragments: [mat(12)][kt(8)*16+nt(16)][lane(32)] of uint2 (b0,b1), fp16
__device__ uint2 g_Bf[12 * 4096];
// h pre-converted to fp16, row-major [NN][128] (256B rows)
__device__ uint4 g_hf[NN * 16];

__global__ void prep_w_kernel(const float* __restrict__ Wtr, const float* __restrict__ Wg1,
                              const float* __restrict__ Wg2){
    int id = blockIdx.x * 256 + threadIdx.x;
    if (id >= 12 * 8 * 16 * 32) return;
    int lane = id & 31, nt = (id >> 5) & 15, kt = (id >> 9) & 7, mat = id >> 12;
    int kk = mat / 3, m = mat % 3;
    const float* W = (m == 0) ? Wtr + (size_t)kk * KD1 * D
                   : (m == 1) ? Wg1 + (size_t)kk * KD1 * D
                              : Wg2 + (size_t)kk * D * D;
    int k0 = kt * 16 + (lane & 3) * 2;
    int n  = nt * 8 + (lane >> 2);
    uint32_t b0 = pkhf(W[(size_t)k0 * D + n],       W[(size_t)(k0 + 1) * D + n]);
    uint32_t b1 = pkhf(W[(size_t)(k0 + 8) * D + n], W[(size_t)(k0 + 9) * D + n]);
    g_Bf[mat * 4096 + (kt * 16 + nt) * 32 + lane] = make_uint2(b0, b1);
}

__global__ void prep_h_kernel(const float* __restrict__ h){
    int id = blockIdx.x * 256 + threadIdx.x;     // one uint4 (8 fp16) per thread
    if (id >= NN * 16) return;
    const float4* src = (const float4*)h + id * 2;
    float4 v0 = src[0], v1 = src[1];
    g_hf[id] = make_uint4(pkhf(v0.x, v0.y), pkhf(v0.z, v0.w),
                          pkhf(v1.x, v1.y), pkhf(v1.z, v1.w));
}

// ---------------- smem map ----------------
#define O_AH   0               // A tile fp16: [kchunk2][row128][64 fp16] swizzled, 32KB
#define O_ST0  32768           // B stage 0: 32KB
#define O_ST1  65536           // B stage 1
#define O_DEG  98304           // float4[128]
#define O_DEGW 100352          // float[2][3][128]
#define O_BIAS 103424          // float[3][128]
#define SM_MMA 104960

static __device__ __forceinline__ void fill_stage(char* dst, int mat, int tid){
    unsigned d0 = stou(dst);
    const char* src = (const char*)(g_Bf + (size_t)mat * 4096);
    #pragma unroll 4
    for (int i = tid; i < 2048; i += 256)
        cp16(d0 + (unsigned)i * 16u, src + (size_t)i * 16);
    cp_commit();
}

// fp16 GEMM: 128x128x128; warp tile 64x32 (wr 0..1, wc 0..3); A,B in smem
static __device__ __forceinline__ void do_gemm(float (*acc)[4], uint32_t aH,
                                               const char* stage, int wr, int wc, int lane)
{
    const uint2* Bf = (const uint2*)stage;
    #pragma unroll
    for (int i = 0; i < 16; ++i)
        #pragma unroll
        for (int j = 0; j < 4; ++j) acc[i][j] = 0.f;

    #pragma unroll 2
    for (int kt = 0; kt < 8; ++kt) {
        uint32_t ah[4][4];
        const int row = wr * 64 + (lane & 15);
        const int kk  = kt * 16 + (lane >> 4) * 8;
        const uint32_t soff = (uint32_t)(kk >> 6) * 16384u;
        #pragma unroll
        for (int mt = 0; mt < 4; ++mt) {
            uint32_t a = soff + sw128((uint32_t)((row + mt * 16) * 128 + (kk & 63) * 2));
            LDSM4(ah[mt], aH + a);
        }
        uint2 b[4];
        #pragma unroll
        for (int nt = 0; nt < 4; ++nt)
            b[nt] = Bf[(kt * 16 + wc * 4 + nt) * 32 + lane];
        #pragma unroll
        for (int mt = 0; mt < 4; ++mt)
            #pragma unroll
            for (int nt = 0; nt < 4; ++nt)
                MMA(acc[mt * 4 + nt], ah[mt], b[nt]);
    }
}

// epilogue: MODE 0 = sigmoid*prod (tr,deg), 1 = relu->A fp16 (g1,deg), 2 = sigmoid*prod (g2)
template<int MODE>
static __device__ __forceinline__ void epi(float (*acc)[4], float* prod,
                                           const float4* DEG, const float* DEGW,
                                           const float* BIAS,
                                           int wr, int wc, int lane, char* AH)
{
    const float* BW = DEGW + (MODE == 1 ? 384 : 0);
    #pragma unroll
    for (int mt = 0; mt < 4; ++mt) {
        const int r0 = wr * 64 + mt * 16 + (lane >> 2);
        float4 dva, dvb;
        if (MODE != 2) { dva = DEG[r0]; dvb = DEG[r0 + 8]; }
        #pragma unroll
        for (int nt = 0; nt < 4; ++nt) {
            const int c0 = wc * 32 + nt * 8 + 2 * (lane & 3);
            const float b0 = BIAS[MODE * 128 + c0], b1 = BIAS[MODE * 128 + c0 + 1];
            float* a = acc[mt * 4 + nt];
            float x0 = a[0] + b0, x1 = a[1] + b1, x2 = a[2] + b0, x3 = a[3] + b1;
            if (MODE != 2) {
                float w00 = BW[c0], w01 = BW[c0 + 1];
                float w10 = BW[128 + c0], w11 = BW[128 + c0 + 1];
                float w20 = BW[256 + c0], w21 = BW[256 + c0 + 1];
                x0 += dva.x * w00 + dva.y * w10 + dva.z * w20;
                x1 += dva.x * w01 + dva.y * w11 + dva.z * w21;
                x2 += dvb.x * w00 + dvb.y * w10 + dvb.z * w20;
                x3 += dvb.x * w01 + dvb.y * w11 + dvb.z * w21;
            }
            if (MODE == 1) {
                uint32_t oa = (uint32_t)(c0 >> 6) * 16384u + sw128((uint32_t)(r0 * 128 + (c0 & 63) * 2));
                *(uint32_t*)(AH + oa) = pkhf(fmaxf(x0, 0.f), fmaxf(x1, 0.f));
                uint32_t ob = (uint32_t)(c0 >> 6) * 16384u + sw128((uint32_t)((r0 + 8) * 128 + (c0 & 63) * 2));
                *(uint32_t*)(AH + ob) = pkhf(fmaxf(x2, 0.f), fmaxf(x3, 0.f));
            } else {
                float* p = prod + (mt * 4 + nt) * 4;
                p[0] *= sigf(x0); p[1] *= sigf(x1); p[2] *= sigf(x2); p[3] *= sigf(x3);
            }
        }
    }
}

// ---------------------------------------------------------------------------
// Fused fp16 warp-MMA kernel. grid = (ceil(E/128), K), 256 threads.
// ---------------------------------------------------------------------------
__global__ void __launch_bounds__(256)
gnn_mma_kernel(const int* __restrict__ pairs,
               const float* __restrict__ degrees, const int* __restrict__ scat,
               const float* __restrict__ W_tr, const float* __restrict__ b_tr,
               const float* __restrict__ W_g1, const float* __restrict__ b_g1,
               const float* __restrict__ b_g2,
               const float* __restrict__ eps, float* __restrict__ out)
{
    extern __shared__ char smc[];
    char* AH = smc + O_AH;
    float4* DEG = (float4*)(smc + O_DEG);
    float* DEGW = (float*)(smc + O_DEGW);
    float* BIAS = (float*)(smc + O_BIAS);

    const int tid = threadIdx.x, lane = tid & 31, warp = tid >> 5;
    const int wr = warp >> 2, wc = warp & 3;
    const int e0 = blockIdx.x * TR, k = blockIdx.y;
    const uint32_t aHs = stou(AH);

    for (int i = tid; i < 384; i += 256) {
        DEGW[i]       = W_tr[(size_t)k * KD1 * D + 128 * D + i];
        DEGW[384 + i] = W_g1[(size_t)k * KD1 * D + 128 * D + i];
    }
    if (tid < 128) {
        BIAS[tid]       = b_tr[k * D + tid];
        BIAS[128 + tid] = b_g1[k * D + tid];
        BIAS[256 + tid] = b_g2[k * D + tid];
    }
    fill_stage(smc + O_ST0, k * 3 + 0, tid);   // tr -> st0

    float prod[64];
    #pragma unroll
    for (int i = 0; i < 64; ++i) prod[i] = 1.0f;
    float acc[16][4];

    for (int it = 0; it < NT; ++it) {
        char* stA = smc + ((it & 1) ? O_ST1 : O_ST0);   // tr (then g2)
        char* stB = smc + ((it & 1) ? O_ST0 : O_ST1);   // g1
        __syncthreads();                        // prev-iter A/stage reads done
        // ---- gather prepped fp16 h rows -> AH via cp.async; deg -> DEG ----
        {
            int r = tid >> 1, hf = tid & 1;
            int e = e0 + r;
            int row = (e < NE) ? pairs[(k * NT + it) * NE + e] : 0;  // invalid rows: dummy data, never used
            const char* src = (const char*)g_hf + (size_t)row * 256 + hf * 128;
            #pragma unroll
            for (int c = 0; c < 8; ++c) {
                int kd = hf * 64 + c * 8;
                uint32_t off = (uint32_t)hf * 16384u + sw128((uint32_t)(r * 128 + (kd & 63) * 2));
                cp16(aHs + off, src + c * 16);
            }
            if (hf == 0) {
                float4 dv = make_float4(0.f, 0.f, 0.f, 0.f);
                if (e < NE) {
                    const float* dp = degrees + ((size_t)(k * NT + it) * NE + e) * NOHL;
                    dv.x = dp[0]; dv.y = dp[1]; dv.z = dp[2];
                }
                DEG[r] = dv;
            }
        }
        cp_commit();
        cp_wait0();          // A tile + stage (tr) resident
        __syncthreads();

        fill_stage(stB, k * 3 + 1, tid);        // g1 -> stB (overlaps GEMM1)
        do_gemm(acc, aHs, stA, wr, wc, lane);   // GEMM1: tr
        cp_wait0(); __syncthreads();            // stB ready; GEMM1 stA reads done
        epi<0>(acc, prod, DEG, DEGW, BIAS, wr, wc, lane, AH);

        fill_stage(stA, k * 3 + 2, tid);        // g2 -> stA (overlaps GEMM2)
        do_gemm(acc, aHs, stB, wr, wc, lane);   // GEMM2: g1
        cp_wait0();
        __syncthreads();                        // all A reads done + stA(g2) ready
        epi<1>(acc, prod, DEG, DEGW, BIAS, wr, wc, lane, AH);   // g1 -> A (fp16)
        __syncthreads();                        // A writes visible; stB reads done

        if (it + 1 < NT) fill_stage(stB, k * 3 + 0, tid);   // tr for next it
        do_gemm(acc, aHs, stA, wr, wc, lane);   // GEMM3: g2
        epi<2>(acc, prod, DEG, DEGW, BIAS, wr, wc, lane, AH);
    }

    // ---- scatter-add ----
    const float sc = 1.0f + __ldg(eps + k);
    #pragma unroll
    for (int mt = 0; mt < 4; ++mt)
        #pragma unroll
        for (int hr = 0; hr < 2; ++hr) {
            int r = wr * 64 + mt * 16 + (lane >> 2) + hr * 8;
            int e = e0 + r;
            if (e < NE) {
                int idx = __ldg(scat + k * NE + e);
                float* base = out + (size_t)idx * D;
                #pragma unroll
                for (int nt = 0; nt < 4; ++nt) {
                    int c0 = wc * 32 + nt * 8 + 2 * (lane & 3);
                    float v0 = prod[(mt * 4 + nt) * 4 + hr * 2] * sc;
                    float v1 = prod[(mt * 4 + nt) * 4 + hr * 2 + 1] * sc;
                    asm volatile("red.global.add.v2.f32 [%0], {%1,%2};"
                                 :: "l"(base + c0), "f"(v0), "f"(v1) : "memory");
                }
            }
        }
}

// ======================= lin kernel (R6-proven) =======================
#define LTILE 128
#define LAST  132
#define LTHR  512
#define L_AS  (D * LAST)
#define L_BUF (D * 64)
#define SM_L  ((L_AS + 2 * L_BUF) * 4)

static __device__ __forceinline__ ull dup2(float v){
    ull r; asm("mov.b64 %0, {%1, %1};" : "=l"(r) : "f"(v)); return r;
}
static __device__ __forceinline__ void upk2(ull v, float &lo, float &hi){
    asm("mov.b64 {%0, %1}, %2;" : "=f"(lo), "=f"(hi) : "l"(v));
}
static __device__ __forceinline__ ull ffma2(ull a, ull b, ull c){
    ull d; asm("fma.rn.f32x2 %0, %1, %2, %3;" : "=l"(d) : "l"(a), "l"(b), "l"(c));
    return d;
}
__global__ void __launch_bounds__(LTHR, 1)
gnn_lin_kernel(const float* __restrict__ h, const float* __restrict__ W,
               const float* __restrict__ b, float* __restrict__ out)
{
    extern __shared__ float sm[];
    float* As = sm; float* buf0 = As + L_AS; float* buf1 = buf0 + L_BUF;
    const int tid = threadIdx.x, lane = tid & 31, rr = (tid >> 5) * 8;
    const int r0 = blockIdx.x * LTILE;
    {
        int r = tid >> 2, sub = tid & 3, row = r0 + r;
        #pragma unroll
        for (int q = 0; q < 8; ++q) {
            const int c = 32 * sub + 4 * q;
            const int pr = r ^ (((c >> 3) & 7) << 2);
            float* dst = As + c * LAST + pr;
            if (row < NN) {
                const float4 v = ((const float4*)(h + (size_t)row * D))[8 * sub + q];
                dst[0] = v.x; dst[LAST] = v.y; dst[2 * LAST] = v.z; dst[3 * LAST] = v.w;
            } else { dst[0] = 0.f; dst[LAST] = 0.f; dst[2 * LAST] = 0.f; dst[3 * LAST] = 0.f; }
        }
    }
    {
        const unsigned d0 = (unsigned)__cvta_generic_to_shared(buf0);
        for (int i = tid; i < D * 16; i += LTHR) {
            const int kk = i >> 4, c = i & 15;
            cp16(d0 + (unsigned)(kk * 64 + c * 4) * 4u, W + kk * D + c * 4);
        }
        cp_commit();
    }
    cp_wait0(); __syncthreads();
    ull acc[4][2];
    #pragma unroll
    for (int hh = 0; hh < 2; ++hh) {
        if (hh == 0) {
            const unsigned d1 = (unsigned)__cvta_generic_to_shared(buf1);
            for (int i = tid; i < D * 16; i += LTHR) {
                const int kk = i >> 4, c = i & 15;
                cp16(d1 + (unsigned)(kk * 64 + c * 4) * 4u, W + kk * D + 64 + c * 4);
            }
            cp_commit();
        }
        #pragma unroll
        for (int rp = 0; rp < 4; ++rp) { acc[rp][0] = 0ull; acc[rp][1] = 0ull; }
        const float* Wh = hh ? buf1 : buf0;
        #pragma unroll 4
        for (int kk = 0; kk < D; ++kk) {
            const int s4 = ((kk >> 3) & 7) << 2;
            const float* Ar = As + kk * LAST;
            const ulonglong2 alo = *(const ulonglong2*)(Ar + (rr ^ s4));
            const ulonglong2 ahi = *(const ulonglong2*)(Ar + ((rr + 4) ^ s4));
            const float2 bv = *(const float2*)(Wh + kk * 64 + 2 * lane);
            const ull b0 = dup2(bv.x), b1 = dup2(bv.y);
            const ull ap[4] = {alo.x, alo.y, ahi.x, ahi.y};
            #pragma unroll
            for (int rp = 0; rp < 4; ++rp) {
                acc[rp][0] = ffma2(ap[rp], b0, acc[rp][0]);
                acc[rp][1] = ffma2(ap[rp], b1, acc[rp][1]);
            }
        }
        const float2 bb = *(const float2*)(b + 64 * hh + 2 * lane);
        #pragma unroll
        for (int rp = 0; rp < 4; ++rp) {
            float l0, h0, l1, h1;
            upk2(acc[rp][0], l0, h0); upk2(acc[rp][1], l1, h1);
            const int row = r0 + rr + 2 * rp;
            if (row < NN)
                *(float2*)(out + (size_t)row * D + 64 * hh + 2 * lane) = make_float2(l0 + bb.x, l1 + bb.y);
            if (row + 1 < NN)
                *(float2*)(out + (size_t)(row + 1) * D + 64 * hh + 2 * lane) = make_float2(h0 + bb.x, h1 + bb.y);
        }
        if (hh == 0) { cp_wait0(); __syncthreads(); }
    }
}

// ---------------------------------------------------------------------------
extern "C" void kernel_launch(void* const* d_in, const int* in_sizes, int n_in,
                              void* d_out, int out_size)
{
    const float* h       = (const float*)d_in[0];
    const int*   pairs   = (const int*)  d_in[1];
    const float* degrees = (const float*)d_in[2];
    const int*   scat    = (const int*)  d_in[3];
    const float* W_lin   = (const float*)d_in[4];
    const float* b_lin   = (const float*)d_in[5];
    const float* W_tr    = (const float*)d_in[6];
    const float* b_tr    = (const float*)d_in[7];
    const float* W_g1    = (const float*)d_in[8];
    const float* b_g1    = (const float*)d_in[9];
    const float* W_g2    = (const float*)d_in[10];
    const float* b_g2    = (const float*)d_in[11];
    const float* eps     = (const float*)d_in[12];
    float* out = (float*)d_out;

    cudaFuncSetAttribute(gnn_lin_kernel, cudaFuncAttributeMaxDynamicSharedMemorySize, SM_L);
    cudaFuncSetAttribute(gnn_mma_kernel, cudaFuncAttributeMaxDynamicSharedMemorySize, SM_MMA);

    prep_w_kernel<<<192, 256>>>(W_tr, W_g1, W_g2);
    prep_h_kernel<<<(NN * 16 + 255) / 256, 256>>>(h);
    gnn_lin_kernel<<<(NN + LTILE - 1) / LTILE, LTHR, SM_L>>>(h, W_lin, b_lin, out);
    dim3 grid((NE + TR - 1) / TR, NK);
    gnn_mma_kernel<<<grid, 256, SM_MMA>>>(pairs, degrees, scat, W_tr, b_tr,
                                          W_g1, b_g1, b_g2, eps, out);
}